// round 2
// baseline (speedup 1.0000x reference)
#include <cuda_runtime.h>
#include <math.h>

// Problem constants
#define E   1024
#define NH  16
#define HD  64
#define SQ  2048          // seq len (T == S)
#define BS  2             // batch
#define TB  (SQ*BS)       // 4096 rows of [T,B,*]
#define BH  (BS*NH)       // 32 batched heads
#define OUT0 ((size_t)SQ*BS*E)   // 4,194,304 floats: first output

// Scratch (allocation-free: __device__ globals)
__device__ float g_q[BH*SQ*HD];
__device__ float g_k[BH*SQ*HD];
__device__ float g_v[BH*SQ*HD];
__device__ float g_ctx[TB*E];
__device__ float g_rowm[BH*SQ];    // per-row softmax max
__device__ float g_rowinv[BH*SQ];  // per-row 1/sum(exp)

// ---------------------------------------------------------------------------
// Kernel 1: QKV projection. C[row, col] = x[row,:] @ W[col,:]^T + bias[col]
// x is [T,B,E] (row = t*B+b), W is [E,E] row-major (per q/k/v slice).
// Output stored directly in [b,h,t,d] layout for attention.
// Tiles: BM=BN=64, BK=16, 256 threads, 4x4 micro.
// ---------------------------------------------------------------------------
__global__ void proj_kernel(const float* __restrict__ qin,
                            const float* __restrict__ kin,
                            const float* __restrict__ vin,
                            const float* __restrict__ w,
                            const float* __restrict__ bias)
{
    int which = blockIdx.z;
    const float* x  = (which == 0) ? qin : (which == 1) ? kin : vin;
    const float* W  = w + (size_t)which * E * E;
    const float* bv = bias + which * E;
    float* outp = (which == 0) ? g_q : (which == 1) ? g_k : g_v;

    __shared__ float As[64][17];
    __shared__ float Bs[16][65];

    int tid = threadIdx.x;
    int tx = tid & 15, ty = tid >> 4;
    int m0 = blockIdx.y * 64, n0 = blockIdx.x * 64;
    int lr = tid >> 2;            // 0..63
    int lk = (tid & 3) << 2;      // 0,4,8,12

    float acc[4][4] = {};

    for (int k0 = 0; k0 < E; k0 += 16) {
        float4 a4 = *(const float4*)(x + (size_t)(m0 + lr) * E + k0 + lk);
        As[lr][lk+0] = a4.x; As[lr][lk+1] = a4.y; As[lr][lk+2] = a4.z; As[lr][lk+3] = a4.w;
        float4 b4 = *(const float4*)(W + (size_t)(n0 + lr) * E + k0 + lk);
        Bs[lk+0][lr] = b4.x; Bs[lk+1][lr] = b4.y; Bs[lk+2][lr] = b4.z; Bs[lk+3][lr] = b4.w;
        __syncthreads();
        #pragma unroll
        for (int k = 0; k < 16; k++) {
            float ar[4], br[4];
            #pragma unroll
            for (int i = 0; i < 4; i++) ar[i] = As[ty*4+i][k];
            #pragma unroll
            for (int j = 0; j < 4; j++) br[j] = Bs[k][tx*4+j];
            #pragma unroll
            for (int i = 0; i < 4; i++)
                #pragma unroll
                for (int j = 0; j < 4; j++)
                    acc[i][j] += ar[i] * br[j];
        }
        __syncthreads();
    }

    #pragma unroll
    for (int i = 0; i < 4; i++) {
        int row = m0 + ty*4 + i;
        int t = row >> 1;         // B == 2
        int b = row & 1;
        #pragma unroll
        for (int j = 0; j < 4; j++) {
            int col = n0 + tx*4 + j;
            int h = col >> 6, d = col & 63;
            outp[(size_t)(((b<<4) + h) * SQ + t) * HD + d] = acc[i][j] + bv[col];
        }
    }
}

// ---------------------------------------------------------------------------
// Kernel 2: scores + online softmax stats (flash-style pass 1).
// One CTA per (bh, 64-row t-tile). Q tile stays in smem; stream K tiles.
// Writes raw scaled scores to attn region, and per-row (max, 1/sum) stats.
// ---------------------------------------------------------------------------
__global__ void scores_stats_kernel(float* __restrict__ attn)
{
    int bh = blockIdx.y;
    int t0 = blockIdx.x * 64;

    __shared__ float Qs[64][65];
    __shared__ float Ks[64][65];
    __shared__ float red_m[64][17];
    __shared__ float red_l[64][17];

    int tid = threadIdx.x;
    int tx = tid & 15, ty = tid >> 4;
    const float* qb = g_q + (size_t)bh * SQ * HD;
    const float* kb = g_k + (size_t)bh * SQ * HD;

    int lr = tid >> 2;            // 0..63
    int lc = (tid & 3) << 4;      // 0,16,32,48

    // Load Q tile once
    #pragma unroll
    for (int u = 0; u < 4; u++) {
        float4 a4 = *(const float4*)(qb + (size_t)(t0 + lr) * HD + lc + u*4);
        Qs[lr][lc+u*4+0] = a4.x; Qs[lr][lc+u*4+1] = a4.y; Qs[lr][lc+u*4+2] = a4.z; Qs[lr][lc+u*4+3] = a4.w;
    }

    const float scale = 0.125f;   // 1/sqrt(64)
    float m[4], l[4];
    #pragma unroll
    for (int i = 0; i < 4; i++) { m[i] = -INFINITY; l[i] = 0.f; }

    for (int s0 = 0; s0 < SQ; s0 += 64) {
        #pragma unroll
        for (int u = 0; u < 4; u++) {
            float4 b4 = *(const float4*)(kb + (size_t)(s0 + lr) * HD + lc + u*4);
            Ks[lr][lc+u*4+0] = b4.x; Ks[lr][lc+u*4+1] = b4.y; Ks[lr][lc+u*4+2] = b4.z; Ks[lr][lc+u*4+3] = b4.w;
        }
        __syncthreads();

        float acc[4][4] = {};
        #pragma unroll
        for (int k = 0; k < 64; k++) {
            float ar[4], br[4];
            #pragma unroll
            for (int i = 0; i < 4; i++) ar[i] = Qs[ty*4+i][k];
            #pragma unroll
            for (int j = 0; j < 4; j++) br[j] = Ks[tx*4+j][k];
            #pragma unroll
            for (int i = 0; i < 4; i++)
                #pragma unroll
                for (int j = 0; j < 4; j++)
                    acc[i][j] += ar[i] * br[j];
        }

        // scale, write raw scores, update running (m, l)
        #pragma unroll
        for (int i = 0; i < 4; i++) {
            int t = t0 + ty*4 + i;
            float s0v = acc[i][0]*scale, s1v = acc[i][1]*scale;
            float s2v = acc[i][2]*scale, s3v = acc[i][3]*scale;
            float* pr = attn + (size_t)(bh * SQ + t) * SQ + s0 + tx*4;
            pr[0] = s0v; pr[1] = s1v; pr[2] = s2v; pr[3] = s3v;
            float tm = fmaxf(fmaxf(s0v, s1v), fmaxf(s2v, s3v));
            float nm = fmaxf(m[i], tm);
            l[i] = l[i] * __expf(m[i] - nm)
                 + __expf(s0v - nm) + __expf(s1v - nm)
                 + __expf(s2v - nm) + __expf(s3v - nm);
            m[i] = nm;
        }
        __syncthreads();
    }

    // combine partial (m,l) across the 16 tx threads per row
    #pragma unroll
    for (int i = 0; i < 4; i++) {
        red_m[ty*4+i][tx] = m[i];
        red_l[ty*4+i][tx] = l[i];
    }
    __syncthreads();
    if (tid < 64) {
        float M = -INFINITY;
        #pragma unroll
        for (int p = 0; p < 16; p++) M = fmaxf(M, red_m[tid][p]);
        float L = 0.f;
        #pragma unroll
        for (int p = 0; p < 16; p++) L += red_l[tid][p] * __expf(red_m[tid][p] - M);
        g_rowm[bh * SQ + t0 + tid]   = M;
        g_rowinv[bh * SQ + t0 + tid] = 1.0f / L;
    }
}

// ---------------------------------------------------------------------------
// Kernel 3: fused normalize + PV.
// Reads raw scores, p = exp(s - m) * inv_l; writes p back to attn (the
// attn_probs output) and accumulates ctx = P @ V.
// ---------------------------------------------------------------------------
__global__ void pv_norm_kernel(float* __restrict__ attn)
{
    int bh = blockIdx.y;
    int t0 = blockIdx.x * 64;
    int b = bh >> 4, h = bh & 15;

    __shared__ float Ps[64][65];
    __shared__ float Vs[64][65];
    __shared__ float sm_m[64];
    __shared__ float sm_inv[64];

    int tid = threadIdx.x;
    int tx = tid & 15, ty = tid >> 4;
    const float* vb = g_v + (size_t)bh * SQ * HD;

    int lr = tid >> 2;
    int lc = (tid & 3) << 4;

    if (tid < 64) {
        sm_m[tid]   = g_rowm[bh * SQ + t0 + tid];
        sm_inv[tid] = g_rowinv[bh * SQ + t0 + tid];
    }
    __syncthreads();

    float rowm = sm_m[lr];
    float rowinv = sm_inv[lr];

    float acc[4][4] = {};

    for (int s0 = 0; s0 < SQ; s0 += 64) {
        float* prow = attn + (size_t)(bh * SQ + t0 + lr) * SQ + s0;
        #pragma unroll
        for (int u = 0; u < 4; u++) {
            float4 p4 = *(const float4*)(prow + lc + u*4);
            p4.x = __expf(p4.x - rowm) * rowinv;
            p4.y = __expf(p4.y - rowm) * rowinv;
            p4.z = __expf(p4.z - rowm) * rowinv;
            p4.w = __expf(p4.w - rowm) * rowinv;
            *(float4*)(prow + lc + u*4) = p4;   // normalized attn_probs out
            Ps[lr][lc+u*4+0] = p4.x; Ps[lr][lc+u*4+1] = p4.y;
            Ps[lr][lc+u*4+2] = p4.z; Ps[lr][lc+u*4+3] = p4.w;
            float4 v4 = *(const float4*)(vb + (size_t)(s0 + lr) * HD + lc + u*4);
            Vs[lr][lc+u*4+0] = v4.x; Vs[lr][lc+u*4+1] = v4.y;
            Vs[lr][lc+u*4+2] = v4.z; Vs[lr][lc+u*4+3] = v4.w;
        }
        __syncthreads();
        #pragma unroll
        for (int k = 0; k < 64; k++) {
            float ar[4], br[4];
            #pragma unroll
            for (int i = 0; i < 4; i++) ar[i] = Ps[ty*4+i][k];
            #pragma unroll
            for (int j = 0; j < 4; j++) br[j] = Vs[k][tx*4+j];
            #pragma unroll
            for (int i = 0; i < 4; i++)
                #pragma unroll
                for (int j = 0; j < 4; j++)
                    acc[i][j] += ar[i] * br[j];
        }
        __syncthreads();
    }

    #pragma unroll
    for (int i = 0; i < 4; i++) {
        int t = t0 + ty*4 + i;
        #pragma unroll
        for (int j = 0; j < 4; j++) {
            int e = h*64 + tx*4 + j;
            g_ctx[(size_t)(t * BS + b) * E + e] = acc[i][j];
        }
    }
}

// ---------------------------------------------------------------------------
// Kernel 4: out projection. out[row, col] = ctx[row,:] @ Wout[col,:]^T + b
// ---------------------------------------------------------------------------
__global__ void outproj_kernel(const float* __restrict__ w,
                               const float* __restrict__ bias,
                               float* __restrict__ out)
{
    __shared__ float As[64][17];
    __shared__ float Bs[16][65];

    int tid = threadIdx.x;
    int tx = tid & 15, ty = tid >> 4;
    int m0 = blockIdx.y * 64, n0 = blockIdx.x * 64;
    int lr = tid >> 2;
    int lk = (tid & 3) << 2;

    float acc[4][4] = {};

    for (int k0 = 0; k0 < E; k0 += 16) {
        float4 a4 = *(const float4*)(g_ctx + (size_t)(m0 + lr) * E + k0 + lk);
        As[lr][lk+0] = a4.x; As[lr][lk+1] = a4.y; As[lr][lk+2] = a4.z; As[lr][lk+3] = a4.w;
        float4 b4 = *(const float4*)(w + (size_t)(n0 + lr) * E + k0 + lk);
        Bs[lk+0][lr] = b4.x; Bs[lk+1][lr] = b4.y; Bs[lk+2][lr] = b4.z; Bs[lk+3][lr] = b4.w;
        __syncthreads();
        #pragma unroll
        for (int k = 0; k < 16; k++) {
            float ar[4], br[4];
            #pragma unroll
            for (int i = 0; i < 4; i++) ar[i] = As[ty*4+i][k];
            #pragma unroll
            for (int j = 0; j < 4; j++) br[j] = Bs[k][tx*4+j];
            #pragma unroll
            for (int i = 0; i < 4; i++)
                #pragma unroll
                for (int j = 0; j < 4; j++)
                    acc[i][j] += ar[i] * br[j];
        }
        __syncthreads();
    }

    #pragma unroll
    for (int i = 0; i < 4; i++) {
        int row = m0 + ty*4 + i;
        #pragma unroll
        for (int j = 0; j < 4; j++) {
            int col = n0 + tx*4 + j;
            out[(size_t)row * E + col] = acc[i][j] + bias[col];
        }
    }
}

// ---------------------------------------------------------------------------
extern "C" void kernel_launch(void* const* d_in, const int* in_sizes, int n_in,
                              void* d_out, int out_size)
{
    const float* q   = (const float*)d_in[0];
    const float* k   = (const float*)d_in[1];
    const float* v   = (const float*)d_in[2];
    const float* inw = (const float*)d_in[3];
    const float* inb = (const float*)d_in[4];
    const float* ow  = (const float*)d_in[5];
    const float* ob  = (const float*)d_in[6];

    float* out  = (float*)d_out;          // [T,B,E] = 4,194,304 floats
    float* attn = out + OUT0;             // [B,H,T,S] = 134,217,728 floats

    // 1) QKV projection (3 GEMMs fused via blockIdx.z)
    proj_kernel<<<dim3(E/64, TB/64, 3), 256>>>(q, k, v, inw, inb);
    // 2) raw scores + online softmax row stats
    scores_stats_kernel<<<dim3(SQ/64, BH), 256>>>(attn);
    // 3) fused normalize + P @ V (writes attn_probs output + ctx)
    pv_norm_kernel<<<dim3(SQ/64, BH), 256>>>(attn);
    // 4) output projection
    outproj_kernel<<<dim3(E/64, TB/64), 256>>>(ow, ob, out);
}

// round 3
// speedup vs baseline: 2.0840x; 2.0840x over previous
#include <cuda_runtime.h>
#include <math.h>

// Problem constants
#define E   1024
#define NH  16
#define HD  64
#define SQ  2048
#define BS  2
#define TB  (SQ*BS)       // 4096
#define BH  (BS*NH)       // 32
#define OUT0 ((size_t)SQ*BS*E)

// Scratch
__device__ float g_q[BH*SQ*HD];
__device__ float g_k[BH*SQ*HD];
__device__ float g_v[BH*SQ*HD];
__device__ float g_ctx[TB*E];
__device__ float g_rowm[BH*SQ];
__device__ float g_rowinv[BH*SQ];

// ---------------------------------------------------------------------------
// tf32 helpers
// ---------------------------------------------------------------------------
__device__ __forceinline__ unsigned f2tf(float f) {
    unsigned r;
    asm("cvt.rna.tf32.f32 %0, %1;" : "=r"(r) : "f"(f));
    return r;
}

__device__ __forceinline__ void mma8(float* c,
                                     unsigned a0, unsigned a1, unsigned a2, unsigned a3,
                                     unsigned b0, unsigned b1) {
    asm volatile(
        "mma.sync.aligned.m16n8k8.row.col.f32.tf32.tf32.f32 "
        "{%0,%1,%2,%3}, {%4,%5,%6,%7}, {%8,%9}, {%0,%1,%2,%3};\n"
        : "+f"(c[0]), "+f"(c[1]), "+f"(c[2]), "+f"(c[3])
        : "r"(a0), "r"(a1), "r"(a2), "r"(a3), "r"(b0), "r"(b1));
}

// ---------------------------------------------------------------------------
// Kernel 1: QKV projection via tf32 MMA.
// C[row,col] = x[row,:] . W[col,:] + bias[col];  BM=128, BN=64, BK=32.
// 8 warps = 4(M) x 2(N); warp tile 32x32 = 2x4 m16n8 mmas; out -> [b,h,t,d].
// ---------------------------------------------------------------------------
__global__ void proj_kernel(const float* __restrict__ qin,
                            const float* __restrict__ kin,
                            const float* __restrict__ vin,
                            const float* __restrict__ w,
                            const float* __restrict__ bias)
{
    int which = blockIdx.z;
    const float* x  = (which == 0) ? qin : (which == 1) ? kin : vin;
    const float* W  = w + (size_t)which * E * E;
    const float* bv = bias + which * E;
    float* outp = (which == 0) ? g_q : (which == 1) ? g_k : g_v;

    __shared__ unsigned As[128][36];   // [m][k], stride 36 = 4 mod 32
    __shared__ unsigned Bs[32][72];    // [k][n], stride 72 = 8 mod 32

    int tid = threadIdx.x;
    int warp = tid >> 5, lane = tid & 31;
    int g = lane >> 2, tg = lane & 3;
    int wm = warp >> 1, wn = warp & 1;
    int m0 = blockIdx.y * 128, n0 = blockIdx.x * 64;

    int lrA = tid >> 1;            // 0..127
    int lcA = (tid & 1) * 16;
    int lrB = tid >> 2;            // 0..63
    int lcB = (tid & 3) * 8;

    float acc[2][4][4] = {};

    for (int k0 = 0; k0 < E; k0 += 32) {
        #pragma unroll
        for (int u = 0; u < 4; u++) {
            float4 a4 = *(const float4*)(x + (size_t)(m0 + lrA) * E + k0 + lcA + u*4);
            uint4 t4 = { f2tf(a4.x), f2tf(a4.y), f2tf(a4.z), f2tf(a4.w) };
            *(uint4*)&As[lrA][lcA + u*4] = t4;
        }
        #pragma unroll
        for (int u = 0; u < 2; u++) {
            float4 b4 = *(const float4*)(W + (size_t)(n0 + lrB) * E + k0 + lcB + u*4);
            Bs[lcB + u*4 + 0][lrB] = f2tf(b4.x);
            Bs[lcB + u*4 + 1][lrB] = f2tf(b4.y);
            Bs[lcB + u*4 + 2][lrB] = f2tf(b4.z);
            Bs[lcB + u*4 + 3][lrB] = f2tf(b4.w);
        }
        __syncthreads();

        #pragma unroll
        for (int kk = 0; kk < 4; kk++) {
            int kb = kk * 8;
            unsigned a[2][4];
            #pragma unroll
            for (int mi = 0; mi < 2; mi++) {
                int r = wm*32 + mi*16 + g;
                a[mi][0] = As[r][kb+tg];     a[mi][1] = As[r+8][kb+tg];
                a[mi][2] = As[r][kb+tg+4];   a[mi][3] = As[r+8][kb+tg+4];
            }
            unsigned b[4][2];
            #pragma unroll
            for (int ni = 0; ni < 4; ni++) {
                int c = wn*32 + ni*8 + g;
                b[ni][0] = Bs[kb+tg][c];
                b[ni][1] = Bs[kb+tg+4][c];
            }
            #pragma unroll
            for (int mi = 0; mi < 2; mi++)
                #pragma unroll
                for (int ni = 0; ni < 4; ni++)
                    mma8(acc[mi][ni], a[mi][0], a[mi][1], a[mi][2], a[mi][3],
                         b[ni][0], b[ni][1]);
        }
        __syncthreads();
    }

    #pragma unroll
    for (int mi = 0; mi < 2; mi++) {
        #pragma unroll
        for (int half = 0; half < 2; half++) {
            int row = m0 + wm*32 + mi*16 + g + half*8;
            int t = row >> 1, b = row & 1;
            #pragma unroll
            for (int ni = 0; ni < 4; ni++) {
                int col = n0 + wn*32 + ni*8 + tg*2;
                int h = col >> 6, d = col & 63;
                float v0 = acc[mi][ni][half*2+0] + bv[col];
                float v1 = acc[mi][ni][half*2+1] + bv[col+1];
                float2 o = {v0, v1};
                *(float2*)&outp[(size_t)(((b<<4) + h) * SQ + t) * HD + d] = o;
            }
        }
    }
}

// ---------------------------------------------------------------------------
// Kernel 2: scores (tf32 MMA) + online softmax stats.
// CTA = (t-tile 64, bh). 8 warps = 2(M) x 4(N); warp tile 32x16.
// Writes raw scaled scores; accumulates per-row (max, sum).
// ---------------------------------------------------------------------------
__global__ void scores_stats_kernel(float* __restrict__ attn)
{
    int t0 = blockIdx.x * 64;
    int bh = blockIdx.y;

    __shared__ unsigned Qs[64][68];    // [t][d]
    __shared__ unsigned Ks[64][72];    // [d][s]  (transposed K tile)
    __shared__ float red_m[64][17];
    __shared__ float red_l[64][17];

    int tid = threadIdx.x;
    int warp = tid >> 5, lane = tid & 31;
    int g = lane >> 2, tg = lane & 3;
    int wm = warp >> 2, wn = warp & 3;

    const float* qb = g_q + (size_t)bh * SQ * HD;
    const float* kb = g_k + (size_t)bh * SQ * HD;

    int lr = tid >> 2;             // 0..63
    int lc = (tid & 3) * 16;

    // Load Q tile once
    #pragma unroll
    for (int u = 0; u < 4; u++) {
        float4 a4 = *(const float4*)(qb + (size_t)(t0 + lr) * HD + lc + u*4);
        uint4 t4 = { f2tf(a4.x), f2tf(a4.y), f2tf(a4.z), f2tf(a4.w) };
        *(uint4*)&Qs[lr][lc + u*4] = t4;
    }

    const float scale = 0.125f;
    float sm[2][2], sl[2][2];
    #pragma unroll
    for (int mi = 0; mi < 2; mi++)
        #pragma unroll
        for (int hf = 0; hf < 2; hf++) { sm[mi][hf] = -INFINITY; sl[mi][hf] = 0.f; }

    for (int s0 = 0; s0 < SQ; s0 += 64) {
        // K tile, transposed into [d][s]
        #pragma unroll
        for (int u = 0; u < 4; u++) {
            float4 b4 = *(const float4*)(kb + (size_t)(s0 + lr) * HD + lc + u*4);
            Ks[lc + u*4 + 0][lr] = f2tf(b4.x);
            Ks[lc + u*4 + 1][lr] = f2tf(b4.y);
            Ks[lc + u*4 + 2][lr] = f2tf(b4.z);
            Ks[lc + u*4 + 3][lr] = f2tf(b4.w);
        }
        __syncthreads();

        float c[2][2][4] = {};
        #pragma unroll
        for (int kk = 0; kk < 8; kk++) {
            int kb8 = kk * 8;
            unsigned a[2][4];
            #pragma unroll
            for (int mi = 0; mi < 2; mi++) {
                int r = wm*32 + mi*16 + g;
                a[mi][0] = Qs[r][kb8+tg];    a[mi][1] = Qs[r+8][kb8+tg];
                a[mi][2] = Qs[r][kb8+tg+4];  a[mi][3] = Qs[r+8][kb8+tg+4];
            }
            unsigned b[2][2];
            #pragma unroll
            for (int ni = 0; ni < 2; ni++) {
                int cix = wn*16 + ni*8 + g;
                b[ni][0] = Ks[kb8+tg][cix];
                b[ni][1] = Ks[kb8+tg+4][cix];
            }
            #pragma unroll
            for (int mi = 0; mi < 2; mi++)
                #pragma unroll
                for (int ni = 0; ni < 2; ni++)
                    mma8(c[mi][ni], a[mi][0], a[mi][1], a[mi][2], a[mi][3],
                         b[ni][0], b[ni][1]);
        }

        // scale + store raw + stats
        #pragma unroll
        for (int mi = 0; mi < 2; mi++) {
            #pragma unroll
            for (int hf = 0; hf < 2; hf++) {
                int tr = wm*32 + mi*16 + g + hf*8;
                float v0 = c[mi][0][hf*2+0] * scale;
                float v1 = c[mi][0][hf*2+1] * scale;
                float v2 = c[mi][1][hf*2+0] * scale;
                float v3 = c[mi][1][hf*2+1] * scale;
                float* pr = attn + (size_t)(bh * SQ + t0 + tr) * SQ + s0 + wn*16 + tg*2;
                *(float2*)(pr)     = make_float2(v0, v1);
                *(float2*)(pr + 8) = make_float2(v2, v3);
                float tm = fmaxf(fmaxf(v0, v1), fmaxf(v2, v3));
                float nm = fmaxf(sm[mi][hf], tm);
                sl[mi][hf] = sl[mi][hf] * __expf(sm[mi][hf] - nm)
                           + __expf(v0 - nm) + __expf(v1 - nm)
                           + __expf(v2 - nm) + __expf(v3 - nm);
                sm[mi][hf] = nm;
            }
        }
        __syncthreads();
    }

    // reduce per-row stats: 16 partials (wn x tg)
    #pragma unroll
    for (int mi = 0; mi < 2; mi++)
        #pragma unroll
        for (int hf = 0; hf < 2; hf++) {
            int tr = wm*32 + mi*16 + g + hf*8;
            red_m[tr][wn*4 + tg] = sm[mi][hf];
            red_l[tr][wn*4 + tg] = sl[mi][hf];
        }
    __syncthreads();
    if (tid < 64) {
        float M = -INFINITY;
        #pragma unroll
        for (int p = 0; p < 16; p++) M = fmaxf(M, red_m[tid][p]);
        float L = 0.f;
        #pragma unroll
        for (int p = 0; p < 16; p++) L += red_l[tid][p] * __expf(red_m[tid][p] - M);
        g_rowm[bh * SQ + t0 + tid]   = M;
        g_rowinv[bh * SQ + t0 + tid] = 1.0f / L;
    }
}

// ---------------------------------------------------------------------------
// Kernel 3: fused normalize + PV (tf32 MMA).
// Reads raw scores, p = exp(s-m)*inv, writes p back (attn_probs output),
// and computes ctx = P @ V.  Warp layout 2(M) x 4(N), N = HD = 64.
// ---------------------------------------------------------------------------
__global__ void pv_norm_kernel(float* __restrict__ attn)
{
    int t0 = blockIdx.x * 64;
    int bh = blockIdx.y;
    int b = bh >> 4, h = bh & 15;

    __shared__ unsigned Ps[64][68];    // [t][s]
    __shared__ unsigned Vs[64][72];    // [s][d]
    __shared__ float sm_m[64];
    __shared__ float sm_inv[64];

    int tid = threadIdx.x;
    int warp = tid >> 5, lane = tid & 31;
    int g = lane >> 2, tg = lane & 3;
    int wm = warp >> 2, wn = warp & 3;

    const float* vb = g_v + (size_t)bh * SQ * HD;
    int lr = tid >> 2;
    int lc = (tid & 3) * 16;

    if (tid < 64) {
        sm_m[tid]   = g_rowm[bh * SQ + t0 + tid];
        sm_inv[tid] = g_rowinv[bh * SQ + t0 + tid];
    }
    __syncthreads();

    float rowm = sm_m[lr];
    float rowinv = sm_inv[lr];

    float acc[2][4][4] = {};

    for (int s0 = 0; s0 < SQ; s0 += 64) {
        float* prow = attn + (size_t)(bh * SQ + t0 + lr) * SQ + s0;
        #pragma unroll
        for (int u = 0; u < 4; u++) {
            float4 p4 = *(const float4*)(prow + lc + u*4);
            p4.x = __expf(p4.x - rowm) * rowinv;
            p4.y = __expf(p4.y - rowm) * rowinv;
            p4.z = __expf(p4.z - rowm) * rowinv;
            p4.w = __expf(p4.w - rowm) * rowinv;
            *(float4*)(prow + lc + u*4) = p4;
            uint4 t4 = { f2tf(p4.x), f2tf(p4.y), f2tf(p4.z), f2tf(p4.w) };
            *(uint4*)&Ps[lr][lc + u*4] = t4;

            float4 v4 = *(const float4*)(vb + (size_t)(s0 + lr) * HD + lc + u*4);
            uint4 tv = { f2tf(v4.x), f2tf(v4.y), f2tf(v4.z), f2tf(v4.w) };
            *(uint4*)&Vs[lr][lc + u*4] = tv;
        }
        __syncthreads();

        #pragma unroll
        for (int kk = 0; kk < 8; kk++) {
            int kb8 = kk * 8;
            unsigned a[2][4];
            #pragma unroll
            for (int mi = 0; mi < 2; mi++) {
                int r = wm*32 + mi*16 + g;
                a[mi][0] = Ps[r][kb8+tg];    a[mi][1] = Ps[r+8][kb8+tg];
                a[mi][2] = Ps[r][kb8+tg+4];  a[mi][3] = Ps[r+8][kb8+tg+4];
            }
            unsigned bb[2][2];
            #pragma unroll
            for (int ni = 0; ni < 2; ni++) {
                int cix = wn*16 + ni*8 + g;
                bb[ni][0] = Vs[kb8+tg][cix];
                bb[ni][1] = Vs[kb8+tg+4][cix];
            }
            #pragma unroll
            for (int mi = 0; mi < 2; mi++)
                #pragma unroll
                for (int ni = 0; ni < 2; ni++)
                    mma8(acc[mi][ni], a[mi][0], a[mi][1], a[mi][2], a[mi][3],
                         bb[ni][0], bb[ni][1]);
        }
        __syncthreads();
    }

    #pragma unroll
    for (int mi = 0; mi < 2; mi++) {
        #pragma unroll
        for (int hf = 0; hf < 2; hf++) {
            int t = t0 + wm*32 + mi*16 + g + hf*8;
            #pragma unroll
            for (int ni = 0; ni < 2; ni++) {
                int d = wn*16 + ni*8 + tg*2;
                float2 o = { acc[mi][ni][hf*2+0], acc[mi][ni][hf*2+1] };
                *(float2*)&g_ctx[(size_t)(t * BS + b) * E + h*64 + d] = o;
            }
        }
    }
}

// ---------------------------------------------------------------------------
// Kernel 4: out projection (tf32 MMA).  Same tiling as proj.
// ---------------------------------------------------------------------------
__global__ void outproj_kernel(const float* __restrict__ w,
                               const float* __restrict__ bias,
                               float* __restrict__ out)
{
    __shared__ unsigned As[128][36];
    __shared__ unsigned Bs[32][72];

    int tid = threadIdx.x;
    int warp = tid >> 5, lane = tid & 31;
    int g = lane >> 2, tg = lane & 3;
    int wm = warp >> 1, wn = warp & 1;
    int m0 = blockIdx.y * 128, n0 = blockIdx.x * 64;

    int lrA = tid >> 1;
    int lcA = (tid & 1) * 16;
    int lrB = tid >> 2;
    int lcB = (tid & 3) * 8;

    float acc[2][4][4] = {};

    for (int k0 = 0; k0 < E; k0 += 32) {
        #pragma unroll
        for (int u = 0; u < 4; u++) {
            float4 a4 = *(const float4*)(g_ctx + (size_t)(m0 + lrA) * E + k0 + lcA + u*4);
            uint4 t4 = { f2tf(a4.x), f2tf(a4.y), f2tf(a4.z), f2tf(a4.w) };
            *(uint4*)&As[lrA][lcA + u*4] = t4;
        }
        #pragma unroll
        for (int u = 0; u < 2; u++) {
            float4 b4 = *(const float4*)(w + (size_t)(n0 + lrB) * E + k0 + lcB + u*4);
            Bs[lcB + u*4 + 0][lrB] = f2tf(b4.x);
            Bs[lcB + u*4 + 1][lrB] = f2tf(b4.y);
            Bs[lcB + u*4 + 2][lrB] = f2tf(b4.z);
            Bs[lcB + u*4 + 3][lrB] = f2tf(b4.w);
        }
        __syncthreads();

        #pragma unroll
        for (int kk = 0; kk < 4; kk++) {
            int kb = kk * 8;
            unsigned a[2][4];
            #pragma unroll
            for (int mi = 0; mi < 2; mi++) {
                int r = wm*32 + mi*16 + g;
                a[mi][0] = As[r][kb+tg];     a[mi][1] = As[r+8][kb+tg];
                a[mi][2] = As[r][kb+tg+4];   a[mi][3] = As[r+8][kb+tg+4];
            }
            unsigned b[4][2];
            #pragma unroll
            for (int ni = 0; ni < 4; ni++) {
                int c = wn*32 + ni*8 + g;
                b[ni][0] = Bs[kb+tg][c];
                b[ni][1] = Bs[kb+tg+4][c];
            }
            #pragma unroll
            for (int mi = 0; mi < 2; mi++)
                #pragma unroll
                for (int ni = 0; ni < 4; ni++)
                    mma8(acc[mi][ni], a[mi][0], a[mi][1], a[mi][2], a[mi][3],
                         b[ni][0], b[ni][1]);
        }
        __syncthreads();
    }

    #pragma unroll
    for (int mi = 0; mi < 2; mi++) {
        #pragma unroll
        for (int hf = 0; hf < 2; hf++) {
            int row = m0 + wm*32 + mi*16 + g + hf*8;
            #pragma unroll
            for (int ni = 0; ni < 4; ni++) {
                int col = n0 + wn*32 + ni*8 + tg*2;
                float2 o = { acc[mi][ni][hf*2+0] + bias[col],
                             acc[mi][ni][hf*2+1] + bias[col+1] };
                *(float2*)&out[(size_t)row * E + col] = o;
            }
        }
    }
}

// ---------------------------------------------------------------------------
extern "C" void kernel_launch(void* const* d_in, const int* in_sizes, int n_in,
                              void* d_out, int out_size)
{
    const float* q   = (const float*)d_in[0];
    const float* k   = (const float*)d_in[1];
    const float* v   = (const float*)d_in[2];
    const float* inw = (const float*)d_in[3];
    const float* inb = (const float*)d_in[4];
    const float* ow  = (const float*)d_in[5];
    const float* ob  = (const float*)d_in[6];

    float* out  = (float*)d_out;
    float* attn = out + OUT0;

    proj_kernel<<<dim3(E/64, TB/128, 3), 256>>>(q, k, v, inw, inb);
    scores_stats_kernel<<<dim3(SQ/64, BH), 256>>>(attn);
    pv_norm_kernel<<<dim3(SQ/64, BH), 256>>>(attn);
    outproj_kernel<<<dim3(E/64, TB/128), 256>>>(ow, ob, out);
}

// round 5
// speedup vs baseline: 2.1695x; 1.0410x over previous
#include <cuda_runtime.h>
#include <math.h>

// Problem constants
#define E   1024
#define NH  16
#define HD  64
#define SQ  2048
#define BS  2
#define TB  (SQ*BS)       // 4096
#define BH  (BS*NH)       // 32
#define OUT0 ((size_t)SQ*BS*E)

// Scratch
__device__ float g_q[BH*SQ*HD];
__device__ float g_k[BH*SQ*HD];
__device__ float g_v[BH*SQ*HD];
__device__ float g_ctx[TB*E];
__device__ float g_rowm[BH*SQ];
__device__ float g_rowinv[BH*SQ];

// ---------------------------------------------------------------------------
// tf32 helpers
// ---------------------------------------------------------------------------
__device__ __forceinline__ unsigned f2tf(float f) {
    unsigned r;
    asm("cvt.rna.tf32.f32 %0, %1;" : "=r"(r) : "f"(f));
    return r;
}

__device__ __forceinline__ void mma8(float* c,
                                     unsigned a0, unsigned a1, unsigned a2, unsigned a3,
                                     unsigned b0, unsigned b1) {
    asm volatile(
        "mma.sync.aligned.m16n8k8.row.col.f32.tf32.tf32.f32 "
        "{%0,%1,%2,%3}, {%4,%5,%6,%7}, {%8,%9}, {%0,%1,%2,%3};\n"
        : "+f"(c[0]), "+f"(c[1]), "+f"(c[2]), "+f"(c[3])
        : "r"(a0), "r"(a1), "r"(a2), "r"(a3), "r"(b0), "r"(b1));
}

// ===========================================================================
// Pipelined 128x128 tf32 GEMM body, BK=16, 8 warps = 2(M) x 4(N),
// warp tile 64x32. A = src[m][k] row-major, B = w[n][k] row-major.
// Used by proj (3 GEMMs via z) and outproj.
// ===========================================================================

// Kernel 1: QKV projection. out -> [b,h,t,d] layout.
__global__ void __launch_bounds__(256) proj_kernel(
    const float* __restrict__ qin,
    const float* __restrict__ kin,
    const float* __restrict__ vin,
    const float* __restrict__ w,
    const float* __restrict__ bias)
{
    int which = blockIdx.z;
    const float* x  = (which == 0) ? qin : (which == 1) ? kin : vin;
    const float* W  = w + (size_t)which * E * E;
    const float* bv = bias + which * E;
    float* outp = (which == 0) ? g_q : (which == 1) ? g_k : g_v;

    __shared__ unsigned As[2][128][20];   // [m][k], stride 20
    __shared__ unsigned Bs[2][16][136];   // [k][n], stride 136

    int tid = threadIdx.x;
    int warp = tid >> 5, lane = tid & 31;
    int g = lane >> 2, tg = lane & 3;
    int wm = warp >> 2, wn = warp & 3;   // wm 0..1 (M), wn 0..3 (N)
    int m0 = blockIdx.y * 128, n0 = blockIdx.x * 128;

    int lr = tid >> 1;            // 0..127
    int lc = (tid & 1) * 8;       // 0 or 8

    float4 ra0, ra1, rb0, rb1;

    const float* aBase = x + (size_t)(m0 + lr) * E + lc;
    const float* bBase = W + (size_t)(n0 + lr) * E + lc;

    // prefetch tile 0
    ra0 = *(const float4*)(aBase);  ra1 = *(const float4*)(aBase + 4);
    rb0 = *(const float4*)(bBase);  rb1 = *(const float4*)(bBase + 4);
    {
        unsigned* ap = &As[0][lr][lc];
        ap[0]=f2tf(ra0.x); ap[1]=f2tf(ra0.y); ap[2]=f2tf(ra0.z); ap[3]=f2tf(ra0.w);
        ap[4]=f2tf(ra1.x); ap[5]=f2tf(ra1.y); ap[6]=f2tf(ra1.z); ap[7]=f2tf(ra1.w);
        Bs[0][lc+0][lr]=f2tf(rb0.x); Bs[0][lc+1][lr]=f2tf(rb0.y);
        Bs[0][lc+2][lr]=f2tf(rb0.z); Bs[0][lc+3][lr]=f2tf(rb0.w);
        Bs[0][lc+4][lr]=f2tf(rb1.x); Bs[0][lc+5][lr]=f2tf(rb1.y);
        Bs[0][lc+6][lr]=f2tf(rb1.z); Bs[0][lc+7][lr]=f2tf(rb1.w);
    }
    __syncthreads();

    float acc[4][4][4] = {};

    #pragma unroll 1
    for (int kt = 0; kt < 64; kt++) {
        int cur = kt & 1;
        if (kt < 63) {
            const float* ap = aBase + (kt+1)*16;
            const float* bp = bBase + (kt+1)*16;
            ra0 = *(const float4*)(ap);  ra1 = *(const float4*)(ap + 4);
            rb0 = *(const float4*)(bp);  rb1 = *(const float4*)(bp + 4);
        }

        #pragma unroll
        for (int kk = 0; kk < 2; kk++) {
            int kb = kk * 8;
            unsigned a[4][4];
            #pragma unroll
            for (int mi = 0; mi < 4; mi++) {
                int r = wm*64 + mi*16 + g;
                a[mi][0] = As[cur][r][kb+tg];    a[mi][1] = As[cur][r+8][kb+tg];
                a[mi][2] = As[cur][r][kb+tg+4];  a[mi][3] = As[cur][r+8][kb+tg+4];
            }
            unsigned b[4][2];
            #pragma unroll
            for (int ni = 0; ni < 4; ni++) {
                int c = wn*32 + ni*8 + g;
                b[ni][0] = Bs[cur][kb+tg][c];
                b[ni][1] = Bs[cur][kb+tg+4][c];
            }
            #pragma unroll
            for (int mi = 0; mi < 4; mi++)
                #pragma unroll
                for (int ni = 0; ni < 4; ni++)
                    mma8(acc[mi][ni], a[mi][0], a[mi][1], a[mi][2], a[mi][3],
                         b[ni][0], b[ni][1]);
        }

        if (kt < 63) {
            int nxt = cur ^ 1;
            unsigned* ap = &As[nxt][lr][lc];
            ap[0]=f2tf(ra0.x); ap[1]=f2tf(ra0.y); ap[2]=f2tf(ra0.z); ap[3]=f2tf(ra0.w);
            ap[4]=f2tf(ra1.x); ap[5]=f2tf(ra1.y); ap[6]=f2tf(ra1.z); ap[7]=f2tf(ra1.w);
            Bs[nxt][lc+0][lr]=f2tf(rb0.x); Bs[nxt][lc+1][lr]=f2tf(rb0.y);
            Bs[nxt][lc+2][lr]=f2tf(rb0.z); Bs[nxt][lc+3][lr]=f2tf(rb0.w);
            Bs[nxt][lc+4][lr]=f2tf(rb1.x); Bs[nxt][lc+5][lr]=f2tf(rb1.y);
            Bs[nxt][lc+6][lr]=f2tf(rb1.z); Bs[nxt][lc+7][lr]=f2tf(rb1.w);
            __syncthreads();
        }
    }

    #pragma unroll
    for (int mi = 0; mi < 4; mi++) {
        #pragma unroll
        for (int hf = 0; hf < 2; hf++) {
            int row = m0 + wm*64 + mi*16 + g + hf*8;
            int t = row >> 1, b = row & 1;
            #pragma unroll
            for (int ni = 0; ni < 4; ni++) {
                int col = n0 + wn*32 + ni*8 + tg*2;
                int h = col >> 6, d = col & 63;
                float2 o = { acc[mi][ni][hf*2+0] + bv[col],
                             acc[mi][ni][hf*2+1] + bv[col+1] };
                *(float2*)&outp[(size_t)(((b<<4) + h) * SQ + t) * HD + d] = o;
            }
        }
    }
}

// ---------------------------------------------------------------------------
// Kernel 2: scores (tf32 MMA) + online softmax stats. (unchanged from r3)
// ---------------------------------------------------------------------------
__global__ void scores_stats_kernel(float* __restrict__ attn)
{
    int t0 = blockIdx.x * 64;
    int bh = blockIdx.y;

    __shared__ unsigned Qs[64][68];
    __shared__ unsigned Ks[64][72];
    __shared__ float red_m[64][17];
    __shared__ float red_l[64][17];

    int tid = threadIdx.x;
    int warp = tid >> 5, lane = tid & 31;
    int g = lane >> 2, tg = lane & 3;
    int wm = warp >> 2, wn = warp & 3;

    const float* qb = g_q + (size_t)bh * SQ * HD;
    const float* kb = g_k + (size_t)bh * SQ * HD;

    int lr = tid >> 2;
    int lc = (tid & 3) * 16;

    #pragma unroll
    for (int u = 0; u < 4; u++) {
        float4 a4 = *(const float4*)(qb + (size_t)(t0 + lr) * HD + lc + u*4);
        uint4 t4 = { f2tf(a4.x), f2tf(a4.y), f2tf(a4.z), f2tf(a4.w) };
        *(uint4*)&Qs[lr][lc + u*4] = t4;
    }

    const float scale = 0.125f;
    float sm[2][2], sl[2][2];
    #pragma unroll
    for (int mi = 0; mi < 2; mi++)
        #pragma unroll
        for (int hf = 0; hf < 2; hf++) { sm[mi][hf] = -INFINITY; sl[mi][hf] = 0.f; }

    for (int s0 = 0; s0 < SQ; s0 += 64) {
        #pragma unroll
        for (int u = 0; u < 4; u++) {
            float4 b4 = *(const float4*)(kb + (size_t)(s0 + lr) * HD + lc + u*4);
            Ks[lc + u*4 + 0][lr] = f2tf(b4.x);
            Ks[lc + u*4 + 1][lr] = f2tf(b4.y);
            Ks[lc + u*4 + 2][lr] = f2tf(b4.z);
            Ks[lc + u*4 + 3][lr] = f2tf(b4.w);
        }
        __syncthreads();

        float c[2][2][4] = {};
        #pragma unroll
        for (int kk = 0; kk < 8; kk++) {
            int kb8 = kk * 8;
            unsigned a[2][4];
            #pragma unroll
            for (int mi = 0; mi < 2; mi++) {
                int r = wm*32 + mi*16 + g;
                a[mi][0] = Qs[r][kb8+tg];    a[mi][1] = Qs[r+8][kb8+tg];
                a[mi][2] = Qs[r][kb8+tg+4];  a[mi][3] = Qs[r+8][kb8+tg+4];
            }
            unsigned b[2][2];
            #pragma unroll
            for (int ni = 0; ni < 2; ni++) {
                int cix = wn*16 + ni*8 + g;
                b[ni][0] = Ks[kb8+tg][cix];
                b[ni][1] = Ks[kb8+tg+4][cix];
            }
            #pragma unroll
            for (int mi = 0; mi < 2; mi++)
                #pragma unroll
                for (int ni = 0; ni < 2; ni++)
                    mma8(c[mi][ni], a[mi][0], a[mi][1], a[mi][2], a[mi][3],
                         b[ni][0], b[ni][1]);
        }

        #pragma unroll
        for (int mi = 0; mi < 2; mi++) {
            #pragma unroll
            for (int hf = 0; hf < 2; hf++) {
                int tr = wm*32 + mi*16 + g + hf*8;
                float v0 = c[mi][0][hf*2+0] * scale;
                float v1 = c[mi][0][hf*2+1] * scale;
                float v2 = c[mi][1][hf*2+0] * scale;
                float v3 = c[mi][1][hf*2+1] * scale;
                float* pr = attn + (size_t)(bh * SQ + t0 + tr) * SQ + s0 + wn*16 + tg*2;
                *(float2*)(pr)     = make_float2(v0, v1);
                *(float2*)(pr + 8) = make_float2(v2, v3);
                float tm = fmaxf(fmaxf(v0, v1), fmaxf(v2, v3));
                float nm = fmaxf(sm[mi][hf], tm);
                sl[mi][hf] = sl[mi][hf] * __expf(sm[mi][hf] - nm)
                           + __expf(v0 - nm) + __expf(v1 - nm)
                           + __expf(v2 - nm) + __expf(v3 - nm);
                sm[mi][hf] = nm;
            }
        }
        __syncthreads();
    }

    #pragma unroll
    for (int mi = 0; mi < 2; mi++)
        #pragma unroll
        for (int hf = 0; hf < 2; hf++) {
            int tr = wm*32 + mi*16 + g + hf*8;
            red_m[tr][wn*4 + tg] = sm[mi][hf];
            red_l[tr][wn*4 + tg] = sl[mi][hf];
        }
    __syncthreads();
    if (tid < 64) {
        float M = -INFINITY;
        #pragma unroll
        for (int p = 0; p < 16; p++) M = fmaxf(M, red_m[tid][p]);
        float L = 0.f;
        #pragma unroll
        for (int p = 0; p < 16; p++) L += red_l[tid][p] * __expf(red_m[tid][p] - M);
        g_rowm[bh * SQ + t0 + tid]   = M;
        g_rowinv[bh * SQ + t0 + tid] = 1.0f / L;
    }
}

// ---------------------------------------------------------------------------
// Kernel 3: fused normalize + PV (tf32 MMA). (unchanged from r3)
// ---------------------------------------------------------------------------
__global__ void pv_norm_kernel(float* __restrict__ attn)
{
    int t0 = blockIdx.x * 64;
    int bh = blockIdx.y;
    int b = bh >> 4, h = bh & 15;

    __shared__ unsigned Ps[64][68];
    __shared__ unsigned Vs[64][72];
    __shared__ float sm_m[64];
    __shared__ float sm_inv[64];

    int tid = threadIdx.x;
    int warp = tid >> 5, lane = tid & 31;
    int g = lane >> 2, tg = lane & 3;
    int wm = warp >> 2, wn = warp & 3;

    const float* vb = g_v + (size_t)bh * SQ * HD;
    int lr = tid >> 2;
    int lc = (tid & 3) * 16;

    if (tid < 64) {
        sm_m[tid]   = g_rowm[bh * SQ + t0 + tid];
        sm_inv[tid] = g_rowinv[bh * SQ + t0 + tid];
    }
    __syncthreads();

    float rowm = sm_m[lr];
    float rowinv = sm_inv[lr];

    float acc[2][4][4] = {};

    for (int s0 = 0; s0 < SQ; s0 += 64) {
        float* prow = attn + (size_t)(bh * SQ + t0 + lr) * SQ + s0;
        #pragma unroll
        for (int u = 0; u < 4; u++) {
            float4 p4 = *(const float4*)(prow + lc + u*4);
            p4.x = __expf(p4.x - rowm) * rowinv;
            p4.y = __expf(p4.y - rowm) * rowinv;
            p4.z = __expf(p4.z - rowm) * rowinv;
            p4.w = __expf(p4.w - rowm) * rowinv;
            *(float4*)(prow + lc + u*4) = p4;
            uint4 t4 = { f2tf(p4.x), f2tf(p4.y), f2tf(p4.z), f2tf(p4.w) };
            *(uint4*)&Ps[lr][lc + u*4] = t4;

            float4 v4 = *(const float4*)(vb + (size_t)(s0 + lr) * HD + lc + u*4);
            uint4 tv = { f2tf(v4.x), f2tf(v4.y), f2tf(v4.z), f2tf(v4.w) };
            *(uint4*)&Vs[lr][lc + u*4] = tv;
        }
        __syncthreads();

        #pragma unroll
        for (int kk = 0; kk < 8; kk++) {
            int kb8 = kk * 8;
            unsigned a[2][4];
            #pragma unroll
            for (int mi = 0; mi < 2; mi++) {
                int r = wm*32 + mi*16 + g;
                a[mi][0] = Ps[r][kb8+tg];    a[mi][1] = Ps[r+8][kb8+tg];
                a[mi][2] = Ps[r][kb8+tg+4];  a[mi][3] = Ps[r+8][kb8+tg+4];
            }
            unsigned bb[2][2];
            #pragma unroll
            for (int ni = 0; ni < 2; ni++) {
                int cix = wn*16 + ni*8 + g;
                bb[ni][0] = Vs[kb8+tg][cix];
                bb[ni][1] = Vs[kb8+tg+4][cix];
            }
            #pragma unroll
            for (int mi = 0; mi < 2; mi++)
                #pragma unroll
                for (int ni = 0; ni < 2; ni++)
                    mma8(acc[mi][ni], a[mi][0], a[mi][1], a[mi][2], a[mi][3],
                         bb[ni][0], bb[ni][1]);
        }
        __syncthreads();
    }

    #pragma unroll
    for (int mi = 0; mi < 2; mi++) {
        #pragma unroll
        for (int hf = 0; hf < 2; hf++) {
            int t = t0 + wm*32 + mi*16 + g + hf*8;
            #pragma unroll
            for (int ni = 0; ni < 2; ni++) {
                int d = wn*16 + ni*8 + tg*2;
                float2 o = { acc[mi][ni][hf*2+0], acc[mi][ni][hf*2+1] };
                *(float2*)&g_ctx[(size_t)(t * BS + b) * E + h*64 + d] = o;
            }
        }
    }
}

// ---------------------------------------------------------------------------
// Kernel 4: out projection — pipelined 128x128 tf32 GEMM.
// ---------------------------------------------------------------------------
__global__ void __launch_bounds__(256) outproj_kernel(
    const float* __restrict__ w,
    const float* __restrict__ bias,
    float* __restrict__ out)
{
    __shared__ unsigned As[2][128][20];
    __shared__ unsigned Bs[2][16][136];

    int tid = threadIdx.x;
    int warp = tid >> 5, lane = tid & 31;
    int g = lane >> 2, tg = lane & 3;
    int wm = warp >> 2, wn = warp & 3;
    int m0 = blockIdx.y * 128, n0 = blockIdx.x * 128;

    int lr = tid >> 1;
    int lc = (tid & 1) * 8;

    float4 ra0, ra1, rb0, rb1;
    const float* aBase = g_ctx + (size_t)(m0 + lr) * E + lc;
    const float* bBase = w + (size_t)(n0 + lr) * E + lc;

    ra0 = *(const float4*)(aBase);  ra1 = *(const float4*)(aBase + 4);
    rb0 = *(const float4*)(bBase);  rb1 = *(const float4*)(bBase + 4);
    {
        unsigned* ap = &As[0][lr][lc];
        ap[0]=f2tf(ra0.x); ap[1]=f2tf(ra0.y); ap[2]=f2tf(ra0.z); ap[3]=f2tf(ra0.w);
        ap[4]=f2tf(ra1.x); ap[5]=f2tf(ra1.y); ap[6]=f2tf(ra1.z); ap[7]=f2tf(ra1.w);
        Bs[0][lc+0][lr]=f2tf(rb0.x); Bs[0][lc+1][lr]=f2tf(rb0.y);
        Bs[0][lc+2][lr]=f2tf(rb0.z); Bs[0][lc+3][lr]=f2tf(rb0.w);
        Bs[0][lc+4][lr]=f2tf(rb1.x); Bs[0][lc+5][lr]=f2tf(rb1.y);
        Bs[0][lc+6][lr]=f2tf(rb1.z); Bs[0][lc+7][lr]=f2tf(rb1.w);
    }
    __syncthreads();

    float acc[4][4][4] = {};

    #pragma unroll 1
    for (int kt = 0; kt < 64; kt++) {
        int cur = kt & 1;
        if (kt < 63) {
            const float* ap = aBase + (kt+1)*16;
            const float* bp = bBase + (kt+1)*16;
            ra0 = *(const float4*)(ap);  ra1 = *(const float4*)(ap + 4);
            rb0 = *(const float4*)(bp);  rb1 = *(const float4*)(bp + 4);
        }

        #pragma unroll
        for (int kk = 0; kk < 2; kk++) {
            int kb = kk * 8;
            unsigned a[4][4];
            #pragma unroll
            for (int mi = 0; mi < 4; mi++) {
                int r = wm*64 + mi*16 + g;
                a[mi][0] = As[cur][r][kb+tg];    a[mi][1] = As[cur][r+8][kb+tg];
                a[mi][2] = As[cur][r][kb+tg+4];  a[mi][3] = As[cur][r+8][kb+tg+4];
            }
            unsigned b[4][2];
            #pragma unroll
            for (int ni = 0; ni < 4; ni++) {
                int c = wn*32 + ni*8 + g;
                b[ni][0] = Bs[cur][kb+tg][c];
                b[ni][1] = Bs[cur][kb+tg+4][c];
            }
            #pragma unroll
            for (int mi = 0; mi < 4; mi++)
                #pragma unroll
                for (int ni = 0; ni < 4; ni++)
                    mma8(acc[mi][ni], a[mi][0], a[mi][1], a[mi][2], a[mi][3],
                         b[ni][0], b[ni][1]);
        }

        if (kt < 63) {
            int nxt = cur ^ 1;
            unsigned* ap = &As[nxt][lr][lc];
            ap[0]=f2tf(ra0.x); ap[1]=f2tf(ra0.y); ap[2]=f2tf(ra0.z); ap[3]=f2tf(ra0.w);
            ap[4]=f2tf(ra1.x); ap[5]=f2tf(ra1.y); ap[6]=f2tf(ra1.z); ap[7]=f2tf(ra1.w);
            Bs[nxt][lc+0][lr]=f2tf(rb0.x); Bs[nxt][lc+1][lr]=f2tf(rb0.y);
            Bs[nxt][lc+2][lr]=f2tf(rb0.z); Bs[nxt][lc+3][lr]=f2tf(rb0.w);
            Bs[nxt][lc+4][lr]=f2tf(rb1.x); Bs[nxt][lc+5][lr]=f2tf(rb1.y);
            Bs[nxt][lc+6][lr]=f2tf(rb1.z); Bs[nxt][lc+7][lr]=f2tf(rb1.w);
            __syncthreads();
        }
    }

    #pragma unroll
    for (int mi = 0; mi < 4; mi++) {
        #pragma unroll
        for (int hf = 0; hf < 2; hf++) {
            int row = m0 + wm*64 + mi*16 + g + hf*8;
            #pragma unroll
            for (int ni = 0; ni < 4; ni++) {
                int col = n0 + wn*32 + ni*8 + tg*2;
                float2 o = { acc[mi][ni][hf*2+0] + bias[col],
                             acc[mi][ni][hf*2+1] + bias[col+1] };
                *(float2*)&out[(size_t)row * E + col] = o;
            }
        }
    }
}

// ---------------------------------------------------------------------------
extern "C" void kernel_launch(void* const* d_in, const int* in_sizes, int n_in,
                              void* d_out, int out_size)
{
    const float* q   = (const float*)d_in[0];
    const float* k   = (const float*)d_in[1];
    const float* v   = (const float*)d_in[2];
    const float* inw = (const float*)d_in[3];
    const float* inb = (const float*)d_in[4];
    const float* ow  = (const float*)d_in[5];
    const float* ob  = (const float*)d_in[6];

    float* out  = (float*)d_out;
    float* attn = out + OUT0;

    proj_kernel<<<dim3(E/128, TB/128, 3), 256>>>(q, k, v, inw, inb);
    scores_stats_kernel<<<dim3(SQ/64, BH), 256>>>(attn);
    pv_norm_kernel<<<dim3(SQ/64, BH), 256>>>(attn);
    outproj_kernel<<<dim3(E/128, TB/128), 256>>>(ow, ob, out);
}

// round 9
// speedup vs baseline: 2.6739x; 1.2325x over previous
#include <cuda_runtime.h>
#include <math.h>

// Problem constants
#define E   1024
#define NH  16
#define HD  64
#define SQ  2048
#define BS  2
#define TB  (SQ*BS)       // 4096
#define BH  (BS*NH)       // 32
#define OUT0 ((size_t)SQ*BS*E)

// Scratch
__device__ float g_q[BH*SQ*HD];
__device__ float g_k[BH*SQ*HD];
__device__ float g_v[BH*SQ*HD];
__device__ float g_ctx[TB*E];
__device__ float g_rowinv[BH*SQ];

// ---------------------------------------------------------------------------
// tf32 helpers
// ---------------------------------------------------------------------------
__device__ __forceinline__ unsigned f2tf(float f) {
    unsigned r;
    asm("cvt.rna.tf32.f32 %0, %1;" : "=r"(r) : "f"(f));
    return r;
}

__device__ __forceinline__ void mma8(float* c,
                                     unsigned a0, unsigned a1, unsigned a2, unsigned a3,
                                     unsigned b0, unsigned b1) {
    asm volatile(
        "mma.sync.aligned.m16n8k8.row.col.f32.tf32.tf32.f32 "
        "{%0,%1,%2,%3}, {%4,%5,%6,%7}, {%8,%9}, {%0,%1,%2,%3};\n"
        : "+f"(c[0]), "+f"(c[1]), "+f"(c[2]), "+f"(c[3])
        : "r"(a0), "r"(a1), "r"(a2), "r"(a3), "r"(b0), "r"(b1));
}

// ===========================================================================
// Kernel 1: QKV projection (pipelined 128x128 tf32 GEMM). (unchanged)
// ===========================================================================
__global__ void __launch_bounds__(256) proj_kernel(
    const float* __restrict__ qin,
    const float* __restrict__ kin,
    const float* __restrict__ vin,
    const float* __restrict__ w,
    const float* __restrict__ bias)
{
    int which = blockIdx.z;
    const float* x  = (which == 0) ? qin : (which == 1) ? kin : vin;
    const float* W  = w + (size_t)which * E * E;
    const float* bv = bias + which * E;
    float* outp = (which == 0) ? g_q : (which == 1) ? g_k : g_v;

    __shared__ unsigned As[2][128][20];
    __shared__ unsigned Bs[2][16][136];

    int tid = threadIdx.x;
    int warp = tid >> 5, lane = tid & 31;
    int g = lane >> 2, tg = lane & 3;
    int wm = warp >> 2, wn = warp & 3;
    int m0 = blockIdx.y * 128, n0 = blockIdx.x * 128;

    int lr = tid >> 1;
    int lc = (tid & 1) * 8;

    float4 ra0, ra1, rb0, rb1;
    const float* aBase = x + (size_t)(m0 + lr) * E + lc;
    const float* bBase = W + (size_t)(n0 + lr) * E + lc;

    ra0 = *(const float4*)(aBase);  ra1 = *(const float4*)(aBase + 4);
    rb0 = *(const float4*)(bBase);  rb1 = *(const float4*)(bBase + 4);
    {
        unsigned* ap = &As[0][lr][lc];
        ap[0]=f2tf(ra0.x); ap[1]=f2tf(ra0.y); ap[2]=f2tf(ra0.z); ap[3]=f2tf(ra0.w);
        ap[4]=f2tf(ra1.x); ap[5]=f2tf(ra1.y); ap[6]=f2tf(ra1.z); ap[7]=f2tf(ra1.w);
        Bs[0][lc+0][lr]=f2tf(rb0.x); Bs[0][lc+1][lr]=f2tf(rb0.y);
        Bs[0][lc+2][lr]=f2tf(rb0.z); Bs[0][lc+3][lr]=f2tf(rb0.w);
        Bs[0][lc+4][lr]=f2tf(rb1.x); Bs[0][lc+5][lr]=f2tf(rb1.y);
        Bs[0][lc+6][lr]=f2tf(rb1.z); Bs[0][lc+7][lr]=f2tf(rb1.w);
    }
    __syncthreads();

    float acc[4][4][4] = {};

    #pragma unroll 1
    for (int kt = 0; kt < 64; kt++) {
        int cur = kt & 1;
        if (kt < 63) {
            const float* ap = aBase + (kt+1)*16;
            const float* bp = bBase + (kt+1)*16;
            ra0 = *(const float4*)(ap);  ra1 = *(const float4*)(ap + 4);
            rb0 = *(const float4*)(bp);  rb1 = *(const float4*)(bp + 4);
        }

        #pragma unroll
        for (int kk = 0; kk < 2; kk++) {
            int kb = kk * 8;
            unsigned a[4][4];
            #pragma unroll
            for (int mi = 0; mi < 4; mi++) {
                int r = wm*64 + mi*16 + g;
                a[mi][0] = As[cur][r][kb+tg];    a[mi][1] = As[cur][r+8][kb+tg];
                a[mi][2] = As[cur][r][kb+tg+4];  a[mi][3] = As[cur][r+8][kb+tg+4];
            }
            unsigned b[4][2];
            #pragma unroll
            for (int ni = 0; ni < 4; ni++) {
                int c = wn*32 + ni*8 + g;
                b[ni][0] = Bs[cur][kb+tg][c];
                b[ni][1] = Bs[cur][kb+tg+4][c];
            }
            #pragma unroll
            for (int mi = 0; mi < 4; mi++)
                #pragma unroll
                for (int ni = 0; ni < 4; ni++)
                    mma8(acc[mi][ni], a[mi][0], a[mi][1], a[mi][2], a[mi][3],
                         b[ni][0], b[ni][1]);
        }

        if (kt < 63) {
            int nxt = cur ^ 1;
            unsigned* ap = &As[nxt][lr][lc];
            ap[0]=f2tf(ra0.x); ap[1]=f2tf(ra0.y); ap[2]=f2tf(ra0.z); ap[3]=f2tf(ra0.w);
            ap[4]=f2tf(ra1.x); ap[5]=f2tf(ra1.y); ap[6]=f2tf(ra1.z); ap[7]=f2tf(ra1.w);
            Bs[nxt][lc+0][lr]=f2tf(rb0.x); Bs[nxt][lc+1][lr]=f2tf(rb0.y);
            Bs[nxt][lc+2][lr]=f2tf(rb0.z); Bs[nxt][lc+3][lr]=f2tf(rb0.w);
            Bs[nxt][lc+4][lr]=f2tf(rb1.x); Bs[nxt][lc+5][lr]=f2tf(rb1.y);
            Bs[nxt][lc+6][lr]=f2tf(rb1.z); Bs[nxt][lc+7][lr]=f2tf(rb1.w);
            __syncthreads();
        }
    }

    #pragma unroll
    for (int mi = 0; mi < 4; mi++) {
        #pragma unroll
        for (int hf = 0; hf < 2; hf++) {
            int row = m0 + wm*64 + mi*16 + g + hf*8;
            int t = row >> 1, b = row & 1;
            #pragma unroll
            for (int ni = 0; ni < 4; ni++) {
                int col = n0 + wn*32 + ni*8 + tg*2;
                int h = col >> 6, d = col & 63;
                float2 o = { acc[mi][ni][hf*2+0] + bv[col],
                             acc[mi][ni][hf*2+1] + bv[col+1] };
                *(float2*)&outp[(size_t)(((b<<4) + h) * SQ + t) * HD + d] = o;
            }
        }
    }
}

// ===========================================================================
// Kernel 2: scores -> exp(s) + row sums.  t-tile 128, s-tile 128.
// Warps 2(M)x4(N), warp tile 64x32.  K double-buffered, register prefetch.
// Dynamic smem: Qs[128][68] | Ks[2][128][68] | red_l[128][17]
// ===========================================================================
#define SC_SMEM_BYTES ((3*128*68 + 128*17) * 4)

__global__ void __launch_bounds__(256) scores_kernel(float* __restrict__ attn)
{
    extern __shared__ __align__(16) unsigned sm[];
    unsigned (*Qs)[68] = reinterpret_cast<unsigned(*)[68]>(sm);
    unsigned (*Ks)[128][68] = reinterpret_cast<unsigned(*)[128][68]>(sm + 128*68);
    float (*red_l)[17] = reinterpret_cast<float(*)[17]>(sm + 3*128*68);

    int tid = threadIdx.x;
    int warp = tid >> 5, lane = tid & 31;
    int g = lane >> 2, tg = lane & 3;
    int wm = warp >> 2, wn = warp & 3;   // wm 0..1 (M), wn 0..3 (N)
    int t0 = blockIdx.x * 128;
    int bh = blockIdx.y;

    const float* qb = g_q + (size_t)bh * SQ * HD;
    const float* kb = g_k + (size_t)bh * SQ * HD;

    int lrow = tid >> 4;          // 0..15
    int lcol = (tid & 15) * 4;    // 0..60

    // Load Q tile (stays resident)
    #pragma unroll
    for (int j = 0; j < 8; j++) {
        int r = j*16 + lrow;
        float4 a4 = *(const float4*)(qb + (size_t)(t0 + r) * HD + lcol);
        uint4 t4 = { f2tf(a4.x), f2tf(a4.y), f2tf(a4.z), f2tf(a4.w) };
        *(uint4*)&Qs[r][lcol] = t4;
    }
    // Load K tile 0
    float4 kr[8];
    #pragma unroll
    for (int j = 0; j < 8; j++)
        kr[j] = *(const float4*)(kb + (size_t)(j*16 + lrow) * HD + lcol);
    #pragma unroll
    for (int j = 0; j < 8; j++) {
        uint4 t4 = { f2tf(kr[j].x), f2tf(kr[j].y), f2tf(kr[j].z), f2tf(kr[j].w) };
        *(uint4*)&Ks[0][j*16 + lrow][lcol] = t4;
    }
    __syncthreads();

    const float scale = 0.125f;
    float l[4][2];
    #pragma unroll
    for (int mi = 0; mi < 4; mi++) { l[mi][0] = 0.f; l[mi][1] = 0.f; }

    #pragma unroll 1
    for (int st = 0; st < 16; st++) {
        int cur = st & 1;
        if (st < 15) {
            const float* kp = kb + (size_t)(st+1) * 128 * HD;
            #pragma unroll
            for (int j = 0; j < 8; j++)
                kr[j] = *(const float4*)(kp + (size_t)(j*16 + lrow) * HD + lcol);
        }

        float c[4][4][4];
        #pragma unroll
        for (int mi = 0; mi < 4; mi++)
            #pragma unroll
            for (int ni = 0; ni < 4; ni++)
                #pragma unroll
                for (int q = 0; q < 4; q++) c[mi][ni][q] = 0.f;

        #pragma unroll
        for (int kk = 0; kk < 8; kk++) {
            int kb8 = kk * 8;
            unsigned a[4][4];
            #pragma unroll
            for (int mi = 0; mi < 4; mi++) {
                int r = wm*64 + mi*16 + g;
                a[mi][0] = Qs[r][kb8+tg];    a[mi][1] = Qs[r+8][kb8+tg];
                a[mi][2] = Qs[r][kb8+tg+4];  a[mi][3] = Qs[r+8][kb8+tg+4];
            }
            unsigned b[4][2];
            #pragma unroll
            for (int ni = 0; ni < 4; ni++) {
                int cx = wn*32 + ni*8 + g;
                b[ni][0] = Ks[cur][cx][kb8+tg];
                b[ni][1] = Ks[cur][cx][kb8+tg+4];
            }
            #pragma unroll
            for (int mi = 0; mi < 4; mi++)
                #pragma unroll
                for (int ni = 0; ni < 4; ni++)
                    mma8(c[mi][ni], a[mi][0], a[mi][1], a[mi][2], a[mi][3],
                         b[ni][0], b[ni][1]);
        }

        // e = exp(scale*s); store; accumulate row sums
        #pragma unroll
        for (int mi = 0; mi < 4; mi++) {
            #pragma unroll
            for (int hf = 0; hf < 2; hf++) {
                int tr = t0 + wm*64 + mi*16 + g + hf*8;
                float* pr = attn + ((size_t)bh*SQ + tr)*SQ + st*128 + wn*32 + tg*2;
                float lacc = 0.f;
                #pragma unroll
                for (int ni = 0; ni < 4; ni++) {
                    float e0 = __expf(c[mi][ni][hf*2+0] * scale);
                    float e1 = __expf(c[mi][ni][hf*2+1] * scale);
                    *(float2*)(pr + ni*8) = make_float2(e0, e1);
                    lacc += e0 + e1;
                }
                l[mi][hf] += lacc;
            }
        }

        if (st < 15) {
            int nxt = cur ^ 1;
            #pragma unroll
            for (int j = 0; j < 8; j++) {
                uint4 t4 = { f2tf(kr[j].x), f2tf(kr[j].y), f2tf(kr[j].z), f2tf(kr[j].w) };
                *(uint4*)&Ks[nxt][j*16 + lrow][lcol] = t4;
            }
            __syncthreads();
        }
    }

    // reduce row sums (16 partials per row)
    #pragma unroll
    for (int mi = 0; mi < 4; mi++)
        #pragma unroll
        for (int hf = 0; hf < 2; hf++) {
            int tr = wm*64 + mi*16 + g + hf*8;
            red_l[tr][wn*4 + tg] = l[mi][hf];
        }
    __syncthreads();
    if (tid < 128) {
        float L = 0.f;
        #pragma unroll
        for (int p = 0; p < 16; p++) L += red_l[tid][p];
        g_rowinv[bh*SQ + t0 + tid] = 1.0f / L;
    }
}

// ===========================================================================
// Kernel 3: normalize (p = e * inv) + write probs + PV MMA.
// t-tile 128, s-step 128.  Warps 4(M)x2(N), warp tile 32x32.
// Dynamic smem: Ps[2][128][132] | Vs[2][128][72] | sinv[128]
// ===========================================================================
#define PV_SMEM_BYTES ((2*128*132 + 2*128*72 + 128) * 4)

__global__ void __launch_bounds__(256) pv_kernel(float* __restrict__ attn)
{
    extern __shared__ __align__(16) unsigned sm[];
    unsigned (*Ps)[128][132] = reinterpret_cast<unsigned(*)[128][132]>(sm);
    unsigned (*Vs)[128][72]  = reinterpret_cast<unsigned(*)[128][72]>(sm + 2*128*132);
    float* sinv = (float*)(sm + 2*128*132 + 2*128*72);

    int tid = threadIdx.x;
    int warp = tid >> 5, lane = tid & 31;
    int g = lane >> 2, tg = lane & 3;
    int wm = warp >> 1, wn = warp & 1;   // wm 0..3 (M), wn 0..1 (N)
    int t0 = blockIdx.x * 128;
    int bh = blockIdx.y;
    int b = bh >> 4, h = bh & 15;

    const float* vb = g_v + (size_t)bh * SQ * HD;
    float* pb0 = attn + ((size_t)bh*SQ + t0) * SQ;

    if (tid < 128) sinv[tid] = g_rowinv[bh*SQ + t0 + tid];
    __syncthreads();

    float4 pr[16], vr[8];

    // prologue: step 0
    #pragma unroll
    for (int j = 0; j < 16; j++)
        pr[j] = *(const float4*)(pb0 + (size_t)(j*8 + (tid>>5)) * SQ + (tid&31)*4);
    #pragma unroll
    for (int j = 0; j < 8; j++)
        vr[j] = *(const float4*)(vb + (size_t)(j*16 + (tid>>4)) * HD + (tid&15)*4);
    #pragma unroll
    for (int j = 0; j < 16; j++) {
        int row = j*8 + (tid>>5);
        float inv = sinv[row];
        float4 p = pr[j];
        p.x *= inv; p.y *= inv; p.z *= inv; p.w *= inv;
        *(float4*)(pb0 + (size_t)row * SQ + (tid&31)*4) = p;
        uint4 t4 = { f2tf(p.x), f2tf(p.y), f2tf(p.z), f2tf(p.w) };
        *(uint4*)&Ps[0][row][(tid&31)*4] = t4;
    }
    #pragma unroll
    for (int j = 0; j < 8; j++) {
        uint4 t4 = { f2tf(vr[j].x), f2tf(vr[j].y), f2tf(vr[j].z), f2tf(vr[j].w) };
        *(uint4*)&Vs[0][j*16 + (tid>>4)][(tid&15)*4] = t4;
    }
    __syncthreads();

    float acc[2][4][4] = {};

    #pragma unroll 1
    for (int st = 0; st < 16; st++) {
        int cur = st & 1;
        if (st < 15) {
            const float* pp = pb0 + (st+1)*128;
            const float* vp = vb + (size_t)(st+1)*128*HD;
            #pragma unroll
            for (int j = 0; j < 16; j++)
                pr[j] = *(const float4*)(pp + (size_t)(j*8 + (tid>>5)) * SQ + (tid&31)*4);
            #pragma unroll
            for (int j = 0; j < 8; j++)
                vr[j] = *(const float4*)(vp + (size_t)(j*16 + (tid>>4)) * HD + (tid&15)*4);
        }

        #pragma unroll
        for (int kk = 0; kk < 16; kk++) {
            int kb8 = kk * 8;
            unsigned a[2][4];
            #pragma unroll
            for (int mi = 0; mi < 2; mi++) {
                int r = wm*32 + mi*16 + g;
                a[mi][0] = Ps[cur][r][kb8+tg];    a[mi][1] = Ps[cur][r+8][kb8+tg];
                a[mi][2] = Ps[cur][r][kb8+tg+4];  a[mi][3] = Ps[cur][r+8][kb8+tg+4];
            }
            unsigned bb[4][2];
            #pragma unroll
            for (int ni = 0; ni < 4; ni++) {
                int cx = wn*32 + ni*8 + g;
                bb[ni][0] = Vs[cur][kb8+tg][cx];
                bb[ni][1] = Vs[cur][kb8+tg+4][cx];
            }
            #pragma unroll
            for (int mi = 0; mi < 2; mi++)
                #pragma unroll
                for (int ni = 0; ni < 4; ni++)
                    mma8(acc[mi][ni], a[mi][0], a[mi][1], a[mi][2], a[mi][3],
                         bb[ni][0], bb[ni][1]);
        }

        if (st < 15) {
            int nxt = cur ^ 1;
            #pragma unroll
            for (int j = 0; j < 16; j++) {
                int row = j*8 + (tid>>5);
                float inv = sinv[row];
                float4 p = pr[j];
                p.x *= inv; p.y *= inv; p.z *= inv; p.w *= inv;
                *(float4*)(pb0 + (size_t)row * SQ + (st+1)*128 + (tid&31)*4) = p;
                uint4 t4 = { f2tf(p.x), f2tf(p.y), f2tf(p.z), f2tf(p.w) };
                *(uint4*)&Ps[nxt][row][(tid&31)*4] = t4;
            }
            #pragma unroll
            for (int j = 0; j < 8; j++) {
                uint4 t4 = { f2tf(vr[j].x), f2tf(vr[j].y), f2tf(vr[j].z), f2tf(vr[j].w) };
                *(uint4*)&Vs[nxt][j*16 + (tid>>4)][(tid&15)*4] = t4;
            }
            __syncthreads();
        }
    }

    #pragma unroll
    for (int mi = 0; mi < 2; mi++)
        #pragma unroll
        for (int hf = 0; hf < 2; hf++) {
            int t = t0 + wm*32 + mi*16 + g + hf*8;
            #pragma unroll
            for (int ni = 0; ni < 4; ni++) {
                int d = wn*32 + ni*8 + tg*2;
                float2 o = { acc[mi][ni][hf*2+0], acc[mi][ni][hf*2+1] };
                *(float2*)&g_ctx[(size_t)(t*BS + b)*E + h*64 + d] = o;
            }
        }
}

// ===========================================================================
// Kernel 4: out projection (pipelined 128x128 tf32 GEMM). (unchanged)
// ===========================================================================
__global__ void __launch_bounds__(256) outproj_kernel(
    const float* __restrict__ w,
    const float* __restrict__ bias,
    float* __restrict__ out)
{
    __shared__ unsigned As[2][128][20];
    __shared__ unsigned Bs[2][16][136];

    int tid = threadIdx.x;
    int warp = tid >> 5, lane = tid & 31;
    int g = lane >> 2, tg = lane & 3;
    int wm = warp >> 2, wn = warp & 3;
    int m0 = blockIdx.y * 128, n0 = blockIdx.x * 128;

    int lr = tid >> 1;
    int lc = (tid & 1) * 8;

    float4 ra0, ra1, rb0, rb1;
    const float* aBase = g_ctx + (size_t)(m0 + lr) * E + lc;
    const float* bBase = w + (size_t)(n0 + lr) * E + lc;

    ra0 = *(const float4*)(aBase);  ra1 = *(const float4*)(aBase + 4);
    rb0 = *(const float4*)(bBase);  rb1 = *(const float4*)(bBase + 4);
    {
        unsigned* ap = &As[0][lr][lc];
        ap[0]=f2tf(ra0.x); ap[1]=f2tf(ra0.y); ap[2]=f2tf(ra0.z); ap[3]=f2tf(ra0.w);
        ap[4]=f2tf(ra1.x); ap[5]=f2tf(ra1.y); ap[6]=f2tf(ra1.z); ap[7]=f2tf(ra1.w);
        Bs[0][lc+0][lr]=f2tf(rb0.x); Bs[0][lc+1][lr]=f2tf(rb0.y);
        Bs[0][lc+2][lr]=f2tf(rb0.z); Bs[0][lc+3][lr]=f2tf(rb0.w);
        Bs[0][lc+4][lr]=f2tf(rb1.x); Bs[0][lc+5][lr]=f2tf(rb1.y);
        Bs[0][lc+6][lr]=f2tf(rb1.z); Bs[0][lc+7][lr]=f2tf(rb1.w);
    }
    __syncthreads();

    float acc[4][4][4] = {};

    #pragma unroll 1
    for (int kt = 0; kt < 64; kt++) {
        int cur = kt & 1;
        if (kt < 63) {
            const float* ap = aBase + (kt+1)*16;
            const float* bp = bBase + (kt+1)*16;
            ra0 = *(const float4*)(ap);  ra1 = *(const float4*)(ap + 4);
            rb0 = *(const float4*)(bp);  rb1 = *(const float4*)(bp + 4);
        }

        #pragma unroll
        for (int kk = 0; kk < 2; kk++) {
            int kb = kk * 8;
            unsigned a[4][4];
            #pragma unroll
            for (int mi = 0; mi < 4; mi++) {
                int r = wm*64 + mi*16 + g;
                a[mi][0] = As[cur][r][kb+tg];    a[mi][1] = As[cur][r+8][kb+tg];
                a[mi][2] = As[cur][r][kb+tg+4];  a[mi][3] = As[cur][r+8][kb+tg+4];
            }
            unsigned b[4][2];
            #pragma unroll
            for (int ni = 0; ni < 4; ni++) {
                int c = wn*32 + ni*8 + g;
                b[ni][0] = Bs[cur][kb+tg][c];
                b[ni][1] = Bs[cur][kb+tg+4][c];
            }
            #pragma unroll
            for (int mi = 0; mi < 4; mi++)
                #pragma unroll
                for (int ni = 0; ni < 4; ni++)
                    mma8(acc[mi][ni], a[mi][0], a[mi][1], a[mi][2], a[mi][3],
                         b[ni][0], b[ni][1]);
        }

        if (kt < 63) {
            int nxt = cur ^ 1;
            unsigned* ap = &As[nxt][lr][lc];
            ap[0]=f2tf(ra0.x); ap[1]=f2tf(ra0.y); ap[2]=f2tf(ra0.z); ap[3]=f2tf(ra0.w);
            ap[4]=f2tf(ra1.x); ap[5]=f2tf(ra1.y); ap[6]=f2tf(ra1.z); ap[7]=f2tf(ra1.w);
            Bs[nxt][lc+0][lr]=f2tf(rb0.x); Bs[nxt][lc+1][lr]=f2tf(rb0.y);
            Bs[nxt][lc+2][lr]=f2tf(rb0.z); Bs[nxt][lc+3][lr]=f2tf(rb0.w);
            Bs[nxt][lc+4][lr]=f2tf(rb1.x); Bs[nxt][lc+5][lr]=f2tf(rb1.y);
            Bs[nxt][lc+6][lr]=f2tf(rb1.z); Bs[nxt][lc+7][lr]=f2tf(rb1.w);
            __syncthreads();
        }
    }

    #pragma unroll
    for (int mi = 0; mi < 4; mi++) {
        #pragma unroll
        for (int hf = 0; hf < 2; hf++) {
            int row = m0 + wm*64 + mi*16 + g + hf*8;
            #pragma unroll
            for (int ni = 0; ni < 4; ni++) {
                int col = n0 + wn*32 + ni*8 + tg*2;
                float2 o = { acc[mi][ni][hf*2+0] + bias[col],
                             acc[mi][ni][hf*2+1] + bias[col+1] };
                *(float2*)&out[(size_t)row * E + col] = o;
            }
        }
    }
}

// ---------------------------------------------------------------------------
extern "C" void kernel_launch(void* const* d_in, const int* in_sizes, int n_in,
                              void* d_out, int out_size)
{
    const float* q   = (const float*)d_in[0];
    const float* k   = (const float*)d_in[1];
    const float* v   = (const float*)d_in[2];
    const float* inw = (const float*)d_in[3];
    const float* inb = (const float*)d_in[4];
    const float* ow  = (const float*)d_in[5];
    const float* ob  = (const float*)d_in[6];

    float* out  = (float*)d_out;
    float* attn = out + OUT0;

    // opt-in large dynamic smem (idempotent; not a stream op, capture-safe)
    cudaFuncSetAttribute(scores_kernel, cudaFuncAttributeMaxDynamicSharedMemorySize, SC_SMEM_BYTES);
    cudaFuncSetAttribute(pv_kernel,     cudaFuncAttributeMaxDynamicSharedMemorySize, PV_SMEM_BYTES);

    proj_kernel<<<dim3(E/128, TB/128, 3), 256>>>(q, k, v, inw, inb);
    scores_kernel<<<dim3(SQ/128, BH), 256, SC_SMEM_BYTES>>>(attn);
    pv_kernel<<<dim3(SQ/128, BH), 256, PV_SMEM_BYTES>>>(attn);
    outproj_kernel<<<dim3(E/128, TB/128), 256>>>(ow, ob, out);
}